// round 4
// baseline (speedup 1.0000x reference)
#include <cuda_runtime.h>
#include <cstddef>

// Problem constants (fixed by the reference: B=64, T=512, S=16, NZ=512)
#define BB 64
#define TT 512
#define SS 16
#define NZ 512
#define TCH 8   // timesteps per block

// Output layout (float32, concatenated flattened reference outputs):
//   cell_input      : [B, T, NZ]     at offset 0
//   reset_input     : [B, T, 2*NZ]   at offset B*T*NZ
//   reset_indicator : [B, T]         at offset B*T*3*NZ   (written as 0.0f / 1.0f)

__global__ __launch_bounds__(NZ / 4, 8)
void soft2frames_kernel(const float* __restrict__ seg_start,  // [S, B]
                        const float* __restrict__ seg_end,    // [S, B]
                        const float* __restrict__ e0_seg,     // [S, B, NZ]
                        const float* __restrict__ eg_seg,     // [S, B, NZ]
                        float* __restrict__ out) {
    const int t0  = blockIdx.x * TCH;  // first timestep of this chunk
    const int b   = blockIdx.y;        // 0..B-1
    const int tid = threadIdx.x;       // 0..127, one float4 lane of NZ

    __shared__ int   sh_sel[TCH];
    __shared__ float sh_inter[TCH];
    __shared__ int   sh_ind[TCH];

    // ---- segment selection: 8 threads, one per timestep (broadcast loads) ----
    if (tid < TCH) {
        const int t = t0 + tid;
        int   sel = -1, ind = 0;
        float st = 0.f, en = 0.f;
#pragma unroll
        for (int s = 0; s < SS; ++s) {
            const float ss = __ldg(&seg_start[s * BB + b]);
            const float se = __ldg(&seg_end[s * BB + b]);
            const int cs = (int)ceilf(ss);
            const int fe = (int)floorf(se);
            if (t >= cs && t <= fe) { sel = s; st = ss; en = se; }  // last wins
            if (min(max(cs, 0), TT - 1) == t) ind = 1;              // gathered scatter
        }
        sh_sel[tid]   = sel;
        sh_ind[tid]   = ind;
        sh_inter[tid] = ((float)t - st) / (en - st + 1e-7f);
    }
    __syncthreads();

    const size_t bt0 = (size_t)b * TT + t0;
    float4* __restrict__ cell4 = (float4*)(out + bt0 * NZ) + tid;
    float4* __restrict__ rst4  = (float4*)(out + (size_t)BB * TT * NZ + bt0 * (2 * NZ)) + tid;

    int    cached = -2;
    float4 e = make_float4(0.f, 0.f, 0.f, 0.f);
    float4 g = make_float4(0.f, 0.f, 0.f, 0.f);

#pragma unroll
    for (int k = 0; k < TCH; ++k) {
        const int sel = sh_sel[k];                 // block-uniform
        if (sel != cached) {                       // block-uniform branch
            if (sel >= 0) {
                const size_t base = ((size_t)sel * BB + b) * NZ;
                e = __ldg((const float4*)(e0_seg + base) + tid);
                g = __ldg((const float4*)(eg_seg + base) + tid);
            } else {
                e = make_float4(0.f, 0.f, 0.f, 0.f);
                g = make_float4(0.f, 0.f, 0.f, 0.f);
            }
            cached = sel;
        }
        if (sel >= 0) {
            const float inter = sh_inter[k];
            float4 c;
            c.x = fmaf(g.x - e.x, inter, e.x);
            c.y = fmaf(g.y - e.y, inter, e.y);
            c.z = fmaf(g.z - e.z, inter, e.z);
            c.w = fmaf(g.w - e.w, inter, e.w);
            cell4[k * (NZ / 4)]            = c;   // cell_input
            rst4[k * (NZ / 2)]             = g;   // reset_input[:, :NZ]  = e_gs
            rst4[k * (NZ / 2) + NZ / 4]    = e;   // reset_input[:, NZ:]  = e_0s
        } else {
            const float4 z = make_float4(0.f, 0.f, 0.f, 0.f);
            cell4[k * (NZ / 4)]         = z;
            rst4[k * (NZ / 2)]          = z;
            rst4[k * (NZ / 2) + NZ / 4] = z;
        }
    }

    if (tid < TCH) {
        out[(size_t)BB * TT * 3 * NZ + bt0 + tid] = (float)sh_ind[tid];  // reset_indicator
    }
}

extern "C" void kernel_launch(void* const* d_in, const int* in_sizes, int n_in,
                              void* d_out, int out_size) {
    const float* seg_start = (const float*)d_in[0];
    const float* seg_end   = (const float*)d_in[1];
    const float* e0_seg    = (const float*)d_in[2];
    const float* eg_seg    = (const float*)d_in[3];
    float* out = (float*)d_out;

    dim3 grid(TT / TCH, BB);
    soft2frames_kernel<<<grid, NZ / 4>>>(seg_start, seg_end, e0_seg, eg_seg, out);
}